// round 2
// baseline (speedup 1.0000x reference)
#include <cuda_runtime.h>
#include <cstdint>

#define Bv   4
#define Nv   512
#define Dv   128
#define Hv   8
#define H2v  16
#define FFv  512
#define ROWS (Bv*Nv)      // 2048
#define GI   4            // query rows per attention block
#define TJ   32           // key tile
#define NJT  (Nv/TJ)      // 16
#define NP   (NJT*GI)     // 64 pipeline phases
#define NTH  512

// ---------------- scratch (device globals; no allocation allowed) ----------
__device__ float g_hn [ROWS*Dv];
__device__ float g_qkv[ROWS*3*Dv];
__device__ float g_y  [ROWS*Dv];
__device__ float g_z  [ROWS*Dv];
__device__ float g_hid[ROWS*FFv];

// ---------------- helpers --------------------------------------------------
__device__ __forceinline__ void ffma2(unsigned long long& d,
                                      unsigned long long a,
                                      unsigned long long b) {
    // packed 2xfp32 FMA (Blackwell FFMA2) — 2x throughput vs scalar FFMA
    asm("fma.rn.f32x2 %0, %1, %2, %0;" : "+l"(d) : "l"(a), "l"(b));
}
__device__ __forceinline__ float2 unpack2(unsigned long long v) {
    float2 r;
    asm("mov.b64 {%0, %1}, %2;" : "=f"(r.x), "=f"(r.y) : "l"(v));
    return r;
}
__device__ __forceinline__ void cpa16(void* s, const void* g) {
    unsigned sa = (unsigned)__cvta_generic_to_shared(s);
    asm volatile("cp.async.cg.shared.global [%0], [%1], 16;" :: "r"(sa), "l"(g));
}
__device__ __forceinline__ void cp_commit() { asm volatile("cp.async.commit_group;"); }
__device__ __forceinline__ void cp_wait1()  { asm volatile("cp.async.wait_group 1;" ::: "memory"); }

// ---------------- rmsnorm (optionally x+add) -------------------------------
__global__ void rmsnorm_k(const float* __restrict__ x, const float* __restrict__ add,
                          const float* __restrict__ w, float* __restrict__ out) {
    int row = blockIdx.x, t = threadIdx.x;
    float v = x[row*Dv + t];
    if (add) v += add[row*Dv + t];
    float ss = v*v;
    #pragma unroll
    for (int off = 16; off; off >>= 1) ss += __shfl_xor_sync(0xffffffffu, ss, off);
    __shared__ float sred[4];
    if ((t & 31) == 0) sred[t >> 5] = ss;
    __syncthreads();
    float tot = sred[0] + sred[1] + sred[2] + sred[3];
    out[row*Dv + t] = v * rsqrtf(tot * (1.0f/Dv) + 1e-5f) * w[t];
}

// ---------------- tiled GEMM 64x64, BK=32, 256 threads ---------------------
template<bool GELU, bool ADDC>
__global__ void gemm64(const float* __restrict__ A, const float* __restrict__ B,
                       const float* __restrict__ Cadd, float* __restrict__ C,
                       int M, int Nn, int K) {
    __shared__ float Ast[32*64];   // [k][m]
    __shared__ float Bs [32*64];   // [k][n]
    int tid = threadIdx.x;
    int bm = blockIdx.y, bn = blockIdx.x;
    int tx = tid & 15, ty = tid >> 4;
    float acc[4][4] = {};
    for (int k0 = 0; k0 < K; k0 += 32) {
        for (int u = tid; u < 512; u += 256) {          // A: 64 rows x 8 float4
            int r = u >> 3, c4 = u & 7;
            float4 a = *(const float4*)&A[(size_t)(bm*64 + r)*K + k0 + c4*4];
            Ast[(c4*4+0)*64 + r] = a.x; Ast[(c4*4+1)*64 + r] = a.y;
            Ast[(c4*4+2)*64 + r] = a.z; Ast[(c4*4+3)*64 + r] = a.w;
        }
        for (int u = tid; u < 512; u += 256) {          // B: 32 rows x 16 float4
            int kk = u >> 4, n4 = u & 15;
            *(float4*)&Bs[kk*64 + n4*4] =
                *(const float4*)&B[(size_t)(k0+kk)*Nn + bn*64 + n4*4];
        }
        __syncthreads();
        #pragma unroll
        for (int kk = 0; kk < 32; kk++) {
            float4 a4 = *(const float4*)&Ast[kk*64 + ty*4];
            float4 b4 = *(const float4*)&Bs [kk*64 + tx*4];
            float av[4] = {a4.x, a4.y, a4.z, a4.w};
            float bv[4] = {b4.x, b4.y, b4.z, b4.w};
            #pragma unroll
            for (int i = 0; i < 4; i++)
                #pragma unroll
                for (int j = 0; j < 4; j++)
                    acc[i][j] = fmaf(av[i], bv[j], acc[i][j]);
        }
        __syncthreads();
    }
    #pragma unroll
    for (int i = 0; i < 4; i++) {
        int r = bm*64 + ty*4 + i;
        #pragma unroll
        for (int j = 0; j < 4; j++) {
            int c = bn*64 + tx*4 + j;
            float v = acc[i][j];
            if (GELU) v = 0.5f * v * (1.0f + erff(v * 0.70710678118654752f));
            if (ADDC) v += Cadd[(size_t)r*Nn + c];
            C[(size_t)r*Nn + c] = v;
        }
    }
}

// ---------------- fused edge-projection + attention ------------------------
// grid: 512 blocks (b in [0,4), 4 query rows each); 512 threads.
// smem: e dbuf 32K | k dbuf 32K | logits 64K | e2 64K | q 2K | We packed 8K
__global__ void __launch_bounds__(NTH, 1) attn_k(
    const float* __restrict__ e, const float* __restrict__ qkv,
    const float* __restrict__ We, float* __restrict__ yout)
{
    extern __shared__ float smem[];
    float*  sm_e  = smem;                    // 2*TJ*Dv = 8192 f
    float*  sm_k  = sm_e  + 2*TJ*Dv;         // 8192 f
    float*  sm_l  = sm_k  + 2*TJ*Dv;         // GI*Nv*Hv = 16384 f
    float*  sm_e2 = sm_l  + GI*Nv*Hv;        // 16384 f
    float*  sm_q  = sm_e2 + GI*Nv*Hv;        // 512 f
    float2* sm_w2 = (float2*)(sm_q + GI*Dv); // 1024 f2

    const int tid = threadIdx.x;
    const int b  = blockIdx.x >> 7;          // 128 blocks per batch
    const int i0 = (blockIdx.x & 127) * GI;

    // q rows (pre-scaled by 1/sqrt(Dh)=0.25)
    {
        int ii = tid >> 7, c = tid & 127;
        sm_q[tid] = qkv[(size_t)(b*Nv + i0 + ii)*384 + c] * 0.25f;
    }
    // W_e packed as k-pairs per output column: sm_w2[h2*64+cp]
    for (int u = tid; u < H2v*64; u += NTH) {
        int h2 = u >> 6, cp = u & 63;
        sm_w2[u] = make_float2(We[(2*cp)*H2v + h2], We[(2*cp+1)*H2v + h2]);
    }

    auto load_e = [&](int jt, int ii, int par) {
        const float* src = e + ((size_t)(b*Nv + i0 + ii)*Nv + jt*TJ)*Dv;
        float* dst = sm_e + par*TJ*Dv;
        #pragma unroll
        for (int u = tid; u < TJ*Dv/4; u += NTH) cpa16(dst + u*4, src + u*4);
    };
    auto load_kv = [&](int jt, int par, int off, float* base) {
        const float* src = qkv + ((size_t)(b*Nv) + jt*TJ)*384 + off;
        float* dst = base + par*TJ*Dv;
        #pragma unroll
        for (int u = tid; u < TJ*Dv/4; u += NTH) {
            int r = u >> 5, c4 = u & 31;
            cpa16(dst + r*Dv + c4*4, src + (size_t)r*384 + c4*4);
        }
    };

    // -------- pipeline: e1/e2 projection + qk logits --------
    load_kv(0, 0, 128, sm_k);
    load_e(0, 0, 0);
    cp_commit();
    for (int p = 0; p < NP; p++) {
        int pn = p + 1;
        if (pn < NP) {
            int jt2 = pn >> 2, ii2 = pn & 3;
            if (ii2 == 0) load_kv(jt2, jt2 & 1, 128, sm_k);
            load_e(jt2, ii2, pn & 1);
        }
        cp_commit();
        cp_wait1();
        __syncthreads();

        const int jt = p >> 2, ii = p & 3, par = p & 1, kpar = (p >> 2) & 1;
        const int h2 = tid & 15, jl = tid >> 4;
        const ulonglong2* er = (const ulonglong2*)(sm_e + par*TJ*Dv + jl*Dv);
        const ulonglong2* wr = (const ulonglong2*)(sm_w2 + h2*64);
        unsigned long long a0 = 0ull, a1 = 0ull;
        #pragma unroll
        for (int kp = 0; kp < 32; kp++) {
            ulonglong2 ev = er[kp], wv = wr[kp];
            ffma2(a0, ev.x, wv.x);
            ffma2(a1, ev.y, wv.y);
        }
        float2 f0 = unpack2(a0), f1 = unpack2(a1);
        float s = (f0.x + f0.y) + (f1.x + f1.y);
        int j = jt*TJ + jl;
        if (h2 < Hv) {
            const unsigned long long* qq =
                (const unsigned long long*)(sm_q + ii*Dv + h2*16);
            const unsigned long long* kk =
                (const unsigned long long*)(sm_k + kpar*TJ*Dv + jl*Dv + h2*16);
            unsigned long long qa = 0ull;
            #pragma unroll
            for (int d2 = 0; d2 < 8; d2++) ffma2(qa, qq[d2], kk[d2]);
            float2 fq = unpack2(qa);
            sm_l[(ii*Nv + j)*Hv + h2] = s + fq.x + fq.y;
        } else {
            sm_e2[(ii*Nv + j)*Hv + (h2 - Hv)] = s;
        }
        __syncthreads();
    }

    // -------- softmax (32 rows of 512, 16 lanes per row) --------
    {
        int r = tid >> 4, g = tid & 15;
        int si = r >> 3, sh = r & 7;
        float* L        = sm_l  + si*Nv*Hv + sh;
        const float* E2 = sm_e2 + si*Nv*Hv + sh;
        float m = -1e30f;
        #pragma unroll
        for (int jj = 0; jj < 32; jj++) m = fmaxf(m, L[(g + jj*16)*Hv]);
        #pragma unroll
        for (int off = 8; off; off >>= 1)
            m = fmaxf(m, __shfl_xor_sync(0xffffffffu, m, off, 16));
        float ssum = 0.f;
        #pragma unroll
        for (int jj = 0; jj < 32; jj++) {
            int idx = (g + jj*16)*Hv;
            float ex = __expf(L[idx] - m);
            L[idx] = ex; ssum += ex;
        }
        #pragma unroll
        for (int off = 8; off; off >>= 1)
            ssum += __shfl_xor_sync(0xffffffffu, ssum, off, 16);
        float inv = 1.0f / ssum;
        #pragma unroll
        for (int jj = 0; jj < 32; jj++) {
            int idx = (g + jj*16)*Hv;
            L[idx] = L[idx] * inv * E2[idx];
        }
    }
    __syncthreads();

    // -------- y = att @ v (v tiles reuse sm_e buffers) --------
    float accy = 0.f;
    const int iy = tid >> 7, cy = tid & 127, hy = cy >> 4;
    load_kv(0, 0, 256, sm_e);
    cp_commit();
    for (int jt = 0; jt < NJT; jt++) {
        if (jt + 1 < NJT) load_kv(jt + 1, (jt + 1) & 1, 256, sm_e);
        cp_commit();
        cp_wait1();
        __syncthreads();
        const float* vt = sm_e + (jt & 1)*TJ*Dv;
        const float* lr = sm_l + (iy*Nv + jt*TJ)*Hv + hy;
        #pragma unroll
        for (int jl = 0; jl < TJ; jl++)
            accy = fmaf(lr[jl*Hv], vt[jl*Dv + cy], accy);
        __syncthreads();
    }
    yout[(size_t)(b*Nv + i0 + iy)*Dv + cy] = accy;
}

// ---------------- host launch ----------------------------------------------
#define ATTN_SMEM ((2*TJ*Dv + 2*TJ*Dv + GI*Nv*Hv + GI*Nv*Hv + GI*Dv)*4 + H2v*64*8)

extern "C" void kernel_launch(void* const* d_in, const int* in_sizes, int n_in,
                              void* d_out, int out_size) {
    const float* h    = (const float*)d_in[0];
    const float* e    = (const float*)d_in[1];
    const float* W_h  = (const float*)d_in[2];
    const float* W_e  = (const float*)d_in[3];
    const float* n1   = (const float*)d_in[4];
    const float* n2   = (const float*)d_in[5];
    const float* W_fc = (const float*)d_in[6];
    const float* W_pr = (const float*)d_in[7];
    float* out = (float*)d_out;

    float *p_hn, *p_qkv, *p_y, *p_z, *p_hid;
    cudaGetSymbolAddress((void**)&p_hn,  g_hn);
    cudaGetSymbolAddress((void**)&p_qkv, g_qkv);
    cudaGetSymbolAddress((void**)&p_y,   g_y);
    cudaGetSymbolAddress((void**)&p_z,   g_z);
    cudaGetSymbolAddress((void**)&p_hid, g_hid);

    cudaFuncSetAttribute(attn_k, cudaFuncAttributeMaxDynamicSharedMemorySize, ATTN_SMEM);

    // 1) hn = rmsnorm(h)
    rmsnorm_k<<<ROWS, Dv>>>(h, nullptr, n1, p_hn);
    // 2) qkv = hn @ W_h          (2048 x 384, K=128)
    gemm64<false,false><<<dim3(384/64, ROWS/64), 256>>>(p_hn, W_h, nullptr, p_qkv,
                                                        ROWS, 3*Dv, Dv);
    // 3) fused edge projection + attention -> y
    attn_k<<<Bv*(Nv/GI), NTH, ATTN_SMEM>>>(e, p_qkv, W_e, p_y);
    // 4) z = rmsnorm(y + h)
    rmsnorm_k<<<ROWS, Dv>>>(p_y, h, n2, p_z);
    // 5) hid = gelu(z @ W_fc)    (2048 x 512, K=128)
    gemm64<true,false><<<dim3(FFv/64, ROWS/64), 256>>>(p_z, W_fc, nullptr, p_hid,
                                                       ROWS, FFv, Dv);
    // 6) out = hid @ W_proj + y  (2048 x 128, K=512)
    gemm64<false,true><<<dim3(Dv/64, ROWS/64), 256>>>(p_hid, W_pr, p_y, out,
                                                      ROWS, Dv, FFv);
}

// round 4
// speedup vs baseline: 3.7249x; 3.7249x over previous
#include <cuda_runtime.h>
#include <cstdint>

#define Bv   4
#define Nv   512
#define Dv   128
#define Hv   8
#define H2v  16
#define FFv  512
#define ROWS (Bv*Nv)      // 2048
#define GI   4            // query rows per attention block
#define TJ   32           // key tile
#define NJT  (Nv/TJ)      // 16
#define NP   (NJT*GI)     // 64 pipeline phases
#define NTH  512
#define LP   9            // padded per-(i,j) stride for logits/e2 (conflict-free)

// ---------------- scratch (device globals; no allocation allowed) ----------
__device__ float g_hn [ROWS*Dv];
__device__ float g_qkv[ROWS*3*Dv];
__device__ float g_y  [ROWS*Dv];
__device__ float g_z  [ROWS*Dv];
__device__ float g_hid[ROWS*FFv];

// ---------------- helpers --------------------------------------------------
__device__ __forceinline__ void ffma2(unsigned long long& d,
                                      unsigned long long a,
                                      unsigned long long b) {
    asm("fma.rn.f32x2 %0, %1, %2, %0;" : "+l"(d) : "l"(a), "l"(b));
}
__device__ __forceinline__ float2 unpack2(unsigned long long v) {
    float2 r;
    asm("mov.b64 {%0, %1}, %2;" : "=f"(r.x), "=f"(r.y) : "l"(v));
    return r;
}
__device__ __forceinline__ void cpa16(void* s, const void* g) {
    unsigned sa = (unsigned)__cvta_generic_to_shared(s);
    asm volatile("cp.async.cg.shared.global [%0], [%1], 16;" :: "r"(sa), "l"(g));
}
__device__ __forceinline__ void cp_commit() { asm volatile("cp.async.commit_group;"); }
__device__ __forceinline__ void cp_wait1()  { asm volatile("cp.async.wait_group 1;" ::: "memory"); }

// ---------------- rmsnorm: warp per row, float4 per lane --------------------
__global__ void rmsnorm_k(const float* __restrict__ x, const float* __restrict__ add,
                          const float* __restrict__ w, float* __restrict__ out) {
    int row  = blockIdx.x * 8 + (threadIdx.x >> 5);
    int lane = threadIdx.x & 31;
    const float4* xr = (const float4*)(x + (size_t)row*Dv);
    float4 v = xr[lane];
    if (add) {
        float4 a = ((const float4*)(add + (size_t)row*Dv))[lane];
        v.x += a.x; v.y += a.y; v.z += a.z; v.w += a.w;
    }
    float ss = v.x*v.x + v.y*v.y + v.z*v.z + v.w*v.w;
    #pragma unroll
    for (int off = 16; off; off >>= 1) ss += __shfl_xor_sync(0xffffffffu, ss, off);
    float s = rsqrtf(ss * (1.0f/Dv) + 1e-5f);
    float4 wv = ((const float4*)w)[lane];
    float4 o = make_float4(v.x*s*wv.x, v.y*s*wv.y, v.z*s*wv.z, v.w*s*wv.w);
    ((float4*)(out + (size_t)row*Dv))[lane] = o;
}

// ---------------- tiled GEMM 64x64, BK=32, 256 threads ---------------------
template<bool GELU, bool ADDC>
__global__ void gemm64(const float* __restrict__ A, const float* __restrict__ B,
                       const float* __restrict__ Cadd, float* __restrict__ C,
                       int M, int Nn, int K) {
    __shared__ float Ast[32*64];   // [k][m]
    __shared__ float Bs [32*64];   // [k][n]
    int tid = threadIdx.x;
    int bm = blockIdx.y, bn = blockIdx.x;
    int tx = tid & 15, ty = tid >> 4;
    float acc[4][4] = {};
    for (int k0 = 0; k0 < K; k0 += 32) {
        for (int u = tid; u < 512; u += 256) {          // A: 64 rows x 8 float4
            int r = u >> 3, c4 = u & 7;
            float4 a = *(const float4*)&A[(size_t)(bm*64 + r)*K + k0 + c4*4];
            Ast[(c4*4+0)*64 + r] = a.x; Ast[(c4*4+1)*64 + r] = a.y;
            Ast[(c4*4+2)*64 + r] = a.z; Ast[(c4*4+3)*64 + r] = a.w;
        }
        for (int u = tid; u < 512; u += 256) {          // B: 32 rows x 16 float4
            int kk = u >> 4, n4 = u & 15;
            *(float4*)&Bs[kk*64 + n4*4] =
                *(const float4*)&B[(size_t)(k0+kk)*Nn + bn*64 + n4*4];
        }
        __syncthreads();
        #pragma unroll
        for (int kk = 0; kk < 32; kk++) {
            float4 a4 = *(const float4*)&Ast[kk*64 + ty*4];
            float4 b4 = *(const float4*)&Bs [kk*64 + tx*4];
            float av[4] = {a4.x, a4.y, a4.z, a4.w};
            float bv[4] = {b4.x, b4.y, b4.z, b4.w};
            #pragma unroll
            for (int i = 0; i < 4; i++)
                #pragma unroll
                for (int j = 0; j < 4; j++)
                    acc[i][j] = fmaf(av[i], bv[j], acc[i][j]);
        }
        __syncthreads();
    }
    #pragma unroll
    for (int i = 0; i < 4; i++) {
        int r = bm*64 + ty*4 + i;
        #pragma unroll
        for (int j = 0; j < 4; j++) {
            int c = bn*64 + tx*4 + j;
            float v = acc[i][j];
            if (GELU) v = 0.5f * v * (1.0f + erff(v * 0.70710678118654752f));
            if (ADDC) v += Cadd[(size_t)r*Nn + c];
            C[(size_t)r*Nn + c] = v;
        }
    }
}

// ---------------- fused edge-projection + attention ------------------------
// grid: 512 blocks (b in [0,4), 4 query rows each); 512 threads.
__global__ void __launch_bounds__(NTH, 1) attn_k(
    const float* __restrict__ e, const float* __restrict__ qkv,
    const float* __restrict__ We, float* __restrict__ yout)
{
    extern __shared__ float smem[];
    float*  sm_e  = smem;                    // 2*TJ*Dv = 8192 f
    float*  sm_k  = sm_e  + 2*TJ*Dv;         // 8192 f
    float*  sm_l  = sm_k  + 2*TJ*Dv;         // GI*Nv*LP = 18432 f
    float*  sm_e2 = sm_l  + GI*Nv*LP;        // 18432 f
    float*  sm_q  = sm_e2 + GI*Nv*LP;        // 512 f
    float2* sm_w2 = (float2*)(sm_q + GI*Dv); // [kp][h2]: 64*16 f2

    const int tid = threadIdx.x;
    const int b  = blockIdx.x >> 7;          // 128 blocks per batch
    const int i0 = (blockIdx.x & 127) * GI;

    // q rows (pre-scaled by 1/sqrt(Dh)=0.25)
    {
        int ii = tid >> 7, c = tid & 127;
        sm_q[tid] = qkv[(size_t)(b*Nv + i0 + ii)*384 + c] * 0.25f;
    }
    // W_e packed k-pair-major: sm_w2[kp*16 + h2] = (We[2kp][h2], We[2kp+1][h2])
    for (int u = tid; u < 64*H2v; u += NTH) {
        int kp = u >> 4, hh = u & 15;
        sm_w2[u] = make_float2(We[(2*kp)*H2v + hh], We[(2*kp+1)*H2v + hh]);
    }

    auto load_e = [&](int jt, int ii, int par) {
        const float* src = e + ((size_t)(b*Nv + i0 + ii)*Nv + jt*TJ)*Dv;
        float* dst = sm_e + par*TJ*Dv;
        #pragma unroll
        for (int u = tid; u < TJ*Dv/4; u += NTH) cpa16(dst + u*4, src + u*4);
    };
    auto load_kv = [&](int jt, int par, int off, float* base) {
        const float* src = qkv + ((size_t)(b*Nv) + jt*TJ)*384 + off;
        float* dst = base + par*TJ*Dv;
        #pragma unroll
        for (int u = tid; u < TJ*Dv/4; u += NTH) {
            int r = u >> 5, c4 = u & 31;
            cpa16(dst + r*Dv + c4*4, src + (size_t)r*384 + c4*4);
        }
    };

    // -------- pipeline: e1/e2 projection + qk logits --------
    load_kv(0, 0, 128, sm_k);
    load_e(0, 0, 0);
    cp_commit();
    const unsigned long long* wql = (const unsigned long long*)sm_w2;
    for (int p = 0; p < NP; p++) {
        int pn = p + 1;
        if (pn < NP) {
            int jt2 = pn >> 2, ii2 = pn & 3;
            if (ii2 == 0) load_kv(jt2, jt2 & 1, 128, sm_k);
            load_e(jt2, ii2, pn & 1);
        }
        cp_commit();
        cp_wait1();
        __syncthreads();

        const int jt = p >> 2, ii = p & 3, par = p & 1, kpar = (p >> 2) & 1;
        const int h2 = tid & 15, jl = tid >> 4;
        const ulonglong2* er = (const ulonglong2*)(sm_e + par*TJ*Dv + jl*Dv);
        unsigned long long a0 = 0ull, a1 = 0ull;
        #pragma unroll
        for (int kp = 0; kp < 32; kp++) {
            ulonglong2 ev = er[kp];
            ffma2(a0, ev.x, wql[(2*kp)*16 + h2]);
            ffma2(a1, ev.y, wql[(2*kp+1)*16 + h2]);
        }
        float2 f0 = unpack2(a0), f1 = unpack2(a1);
        float s = (f0.x + f0.y) + (f1.x + f1.y);
        int j = jt*TJ + jl;
        if (h2 < Hv) {
            const unsigned long long* qq =
                (const unsigned long long*)(sm_q + ii*Dv + h2*16);
            const unsigned long long* kk =
                (const unsigned long long*)(sm_k + kpar*TJ*Dv + jl*Dv + h2*16);
            unsigned long long qa = 0ull;
            #pragma unroll
            for (int d2 = 0; d2 < 8; d2++) ffma2(qa, qq[d2], kk[d2]);
            float2 fq = unpack2(qa);
            sm_l[(ii*Nv + j)*LP + h2] = s + fq.x + fq.y;
        } else {
            sm_e2[(ii*Nv + j)*LP + (h2 - Hv)] = s;
        }
        __syncthreads();
    }

    // -------- softmax (32 (i,h) rows of 512, 16 lanes per row) --------
    {
        int r = tid >> 4, g = tid & 15;
        int si = r >> 3, sh = r & 7;
        float* L        = sm_l  + si*Nv*LP + sh;
        const float* E2 = sm_e2 + si*Nv*LP + sh;
        float m = -1e30f;
        #pragma unroll
        for (int jj = 0; jj < 32; jj++) m = fmaxf(m, L[(g + jj*16)*LP]);
        #pragma unroll
        for (int off = 8; off; off >>= 1)
            m = fmaxf(m, __shfl_xor_sync(0xffffffffu, m, off, 16));
        float ssum = 0.f;
        #pragma unroll
        for (int jj = 0; jj < 32; jj++) {
            int idx = (g + jj*16)*LP;
            float ex = __expf(L[idx] - m);
            L[idx] = ex; ssum += ex;
        }
        #pragma unroll
        for (int off = 8; off; off >>= 1)
            ssum += __shfl_xor_sync(0xffffffffu, ssum, off, 16);
        float inv = 1.0f / ssum;
        #pragma unroll
        for (int jj = 0; jj < 32; jj++) {
            int idx = (g + jj*16)*LP;
            L[idx] = L[idx] * inv * E2[idx];
        }
    }
    __syncthreads();

    // -------- y = att @ v (v tiles reuse sm_e buffers) --------
    float accy = 0.f;
    const int iy = tid >> 7, cy = tid & 127, hy = cy >> 4;
    load_kv(0, 0, 256, sm_e);
    cp_commit();
    for (int jt = 0; jt < NJT; jt++) {
        if (jt + 1 < NJT) load_kv(jt + 1, (jt + 1) & 1, 256, sm_e);
        cp_commit();
        cp_wait1();
        __syncthreads();
        const float* vt = sm_e + (jt & 1)*TJ*Dv;
        const float* lr = sm_l + (iy*Nv + jt*TJ)*LP + hy;
        #pragma unroll
        for (int jl = 0; jl < TJ; jl++)
            accy = fmaf(lr[jl*LP], vt[jl*Dv + cy], accy);
        __syncthreads();
    }
    yout[(size_t)(b*Nv + i0 + iy)*Dv + cy] = accy;
}

// ---------------- host launch ----------------------------------------------
#define ATTN_SMEM ((2*TJ*Dv + 2*TJ*Dv + 2*GI*Nv*LP + GI*Dv)*4 + 64*H2v*8)

extern "C" void kernel_launch(void* const* d_in, const int* in_sizes, int n_in,
                              void* d_out, int out_size) {
    const float* h    = (const float*)d_in[0];
    const float* e    = (const float*)d_in[1];
    const float* W_h  = (const float*)d_in[2];
    const float* W_e  = (const float*)d_in[3];
    const float* n1   = (const float*)d_in[4];
    const float* n2   = (const float*)d_in[5];
    const float* W_fc = (const float*)d_in[6];
    const float* W_pr = (const float*)d_in[7];
    float* out = (float*)d_out;

    float *p_hn, *p_qkv, *p_y, *p_z, *p_hid;
    cudaGetSymbolAddress((void**)&p_hn,  g_hn);
    cudaGetSymbolAddress((void**)&p_qkv, g_qkv);
    cudaGetSymbolAddress((void**)&p_y,   g_y);
    cudaGetSymbolAddress((void**)&p_z,   g_z);
    cudaGetSymbolAddress((void**)&p_hid, g_hid);

    cudaFuncSetAttribute(attn_k, cudaFuncAttributeMaxDynamicSharedMemorySize, ATTN_SMEM);

    // 1) hn = rmsnorm(h)
    rmsnorm_k<<<ROWS/8, 256>>>(h, nullptr, n1, p_hn);
    // 2) qkv = hn @ W_h          (2048 x 384, K=128)
    gemm64<false,false><<<dim3(384/64, ROWS/64), 256>>>(p_hn, W_h, nullptr, p_qkv,
                                                        ROWS, 3*Dv, Dv);
    // 3) fused edge projection + attention -> y
    attn_k<<<Bv*(Nv/GI), NTH, ATTN_SMEM>>>(e, p_qkv, W_e, p_y);
    // 4) z = rmsnorm(y + h)
    rmsnorm_k<<<ROWS/8, 256>>>(p_y, h, n2, p_z);
    // 5) hid = gelu(z @ W_fc)    (2048 x 512, K=128)
    gemm64<true,false><<<dim3(FFv/64, ROWS/64), 256>>>(p_z, W_fc, nullptr, p_hid,
                                                       ROWS, FFv, Dv);
    // 6) out = hid @ W_proj + y  (2048 x 128, K=512)
    gemm64<false,true><<<dim3(Dv/64, ROWS/64), 256>>>(p_hid, W_pr, p_y, out,
                                                      ROWS, Dv, FFv);
}

// round 5
// speedup vs baseline: 5.7473x; 1.5429x over previous
#include <cuda_runtime.h>
#include <cstdint>

#define Bv   4
#define Nv   512
#define Dv   128
#define Hv   8
#define FFv  512
#define ROWS (Bv*Nv)            // 2048
#define EROWS (Bv*Nv*Nv)        // 1,048,576 rows of e
#define P1_TILE 128
#define P1_AS   132             // padded A row stride (floats): banks 4g+t, 16B aligned
#define P1_NT   8192            // EROWS / P1_TILE

// ---------------- scratch ---------------------------------------------------
__device__ float g_hn [ROWS*Dv];
__device__ float g_qkv[ROWS*3*Dv];
__device__ float g_y  [ROWS*Dv];
__device__ float g_z  [ROWS*Dv];
__device__ float g_hid[ROWS*FFv];
__device__ float g_e12[(size_t)EROWS*16];   // 64 MB: [row][h*2 + {e1,e2}]

// ---------------- helpers ---------------------------------------------------
__device__ __forceinline__ void cpa16(void* s, const void* g) {
    unsigned sa = (unsigned)__cvta_generic_to_shared(s);
    asm volatile("cp.async.cg.shared.global [%0], [%1], 16;" :: "r"(sa), "l"(g));
}
__device__ __forceinline__ void cp_commit() { asm volatile("cp.async.commit_group;"); }
__device__ __forceinline__ void cp_wait1()  { asm volatile("cp.async.wait_group 1;" ::: "memory"); }

__device__ __forceinline__ unsigned cvt_tf32(float x) {
    unsigned u; asm("cvt.rna.tf32.f32 %0, %1;" : "=r"(u) : "f"(x)); return u;
}
__device__ __forceinline__ void mma_tf32(float c[4], const unsigned a[4],
                                         unsigned b0, unsigned b1) {
    asm volatile("mma.sync.aligned.m16n8k8.row.col.f32.tf32.tf32.f32 "
                 "{%0,%1,%2,%3},{%4,%5,%6,%7},{%8,%9},{%0,%1,%2,%3};"
                 : "+f"(c[0]), "+f"(c[1]), "+f"(c[2]), "+f"(c[3])
                 : "r"(a[0]), "r"(a[1]), "r"(a[2]), "r"(a[3]), "r"(b0), "r"(b1));
}

// ---------------- rmsnorm: warp per row -------------------------------------
__global__ void rmsnorm_k(const float* __restrict__ x, const float* __restrict__ add,
                          const float* __restrict__ w, float* __restrict__ out) {
    int row  = blockIdx.x * 8 + (threadIdx.x >> 5);
    int lane = threadIdx.x & 31;
    float4 v = ((const float4*)(x + (size_t)row*Dv))[lane];
    if (add) {
        float4 a = ((const float4*)(add + (size_t)row*Dv))[lane];
        v.x += a.x; v.y += a.y; v.z += a.z; v.w += a.w;
    }
    float ss = v.x*v.x + v.y*v.y + v.z*v.z + v.w*v.w;
    #pragma unroll
    for (int off = 16; off; off >>= 1) ss += __shfl_xor_sync(0xffffffffu, ss, off);
    float s = rsqrtf(ss * (1.0f/Dv) + 1e-5f);
    float4 wv = ((const float4*)w)[lane];
    ((float4*)(out + (size_t)row*Dv))[lane] =
        make_float4(v.x*s*wv.x, v.y*s*wv.y, v.z*s*wv.z, v.w*s*wv.w);
}

// ---------------- tiled GEMM 64x64, BK=32, 256 threads ----------------------
template<bool GELU, bool ADDC>
__global__ void gemm64(const float* __restrict__ A, const float* __restrict__ B,
                       const float* __restrict__ Cadd, float* __restrict__ C,
                       int M, int Nn, int K) {
    __shared__ float Ast[32*64];
    __shared__ float Bs [32*64];
    int tid = threadIdx.x;
    int bm = blockIdx.y, bn = blockIdx.x;
    int tx = tid & 15, ty = tid >> 4;
    float acc[4][4] = {};
    for (int k0 = 0; k0 < K; k0 += 32) {
        for (int u = tid; u < 512; u += 256) {
            int r = u >> 3, c4 = u & 7;
            float4 a = *(const float4*)&A[(size_t)(bm*64 + r)*K + k0 + c4*4];
            Ast[(c4*4+0)*64 + r] = a.x; Ast[(c4*4+1)*64 + r] = a.y;
            Ast[(c4*4+2)*64 + r] = a.z; Ast[(c4*4+3)*64 + r] = a.w;
        }
        for (int u = tid; u < 512; u += 256) {
            int kk = u >> 4, n4 = u & 15;
            *(float4*)&Bs[kk*64 + n4*4] =
                *(const float4*)&B[(size_t)(k0+kk)*Nn + bn*64 + n4*4];
        }
        __syncthreads();
        #pragma unroll
        for (int kk = 0; kk < 32; kk++) {
            float4 a4 = *(const float4*)&Ast[kk*64 + ty*4];
            float4 b4 = *(const float4*)&Bs [kk*64 + tx*4];
            float av[4] = {a4.x, a4.y, a4.z, a4.w};
            float bv[4] = {b4.x, b4.y, b4.z, b4.w};
            #pragma unroll
            for (int i = 0; i < 4; i++)
                #pragma unroll
                for (int j = 0; j < 4; j++)
                    acc[i][j] = fmaf(av[i], bv[j], acc[i][j]);
        }
        __syncthreads();
    }
    #pragma unroll
    for (int i = 0; i < 4; i++) {
        int r = bm*64 + ty*4 + i;
        #pragma unroll
        for (int j = 0; j < 4; j++) {
            int c = bn*64 + tx*4 + j;
            float v = acc[i][j];
            if (GELU) v = 0.5f * v * (1.0f + erff(v * 0.70710678118654752f));
            if (ADDC) v += Cadd[(size_t)r*Nn + c];
            C[(size_t)r*Nn + c] = v;
        }
    }
}

// ---------------- PASS 1: e12 = e @ W_e (tf32 mma, 3-term hi/lo) -----------
// Output column order n: e12[row][n] with n = h*2 + which  (which: 0=e1, 1=e2)
// so We column for logical n is  (n&1)*Hv + (n>>1).
#define P1_SMEM ((2*P1_TILE*P1_AS + 16*2*2*32)*4)

__global__ void __launch_bounds__(256, 1) eproj_k(
    const float* __restrict__ e, const float* __restrict__ We,
    float* __restrict__ e12)
{
    extern __shared__ float sm[];
    float* As  = sm;                          // 2 * 128*132
    float* blo = sm + 2*P1_TILE*P1_AS;        // [16][2][2][32]

    const int tid  = threadIdx.x;
    const int warp = tid >> 5, lane = tid & 31;
    const int g = lane >> 2, t = lane & 3;

    // B fragments: hi in regs, lo in smem (per-lane layout, conflict-free)
    unsigned bhi[16][2][2];
    #pragma unroll
    for (int kk = 0; kk < 16; kk++)
        #pragma unroll
        for (int nt = 0; nt < 2; nt++)
            #pragma unroll
            for (int r = 0; r < 2; r++) {
                int k = kk*8 + t + r*4;
                int n = nt*8 + g;                       // logical output col
                int wcol = (n & 1)*Hv + (n >> 1);       // permuted We column
                float w = We[k*16 + wcol];
                unsigned hi = cvt_tf32(w);
                bhi[kk][nt][r] = hi;
                if (warp == 0) {
                    unsigned lo = cvt_tf32(w - __uint_as_float(hi));
                    blo[((kk*2 + nt)*2 + r)*32 + lane] = __uint_as_float(lo);
                }
            }
    __syncthreads();

    auto load_tile = [&](int tile, int par) {
        const float4* src = (const float4*)(e + (size_t)tile*P1_TILE*Dv);
        float* dst = As + par*P1_TILE*P1_AS;
        #pragma unroll
        for (int u = tid; u < P1_TILE*32; u += 256) {
            int r = u >> 5, c4 = u & 31;
            cpa16(dst + r*P1_AS + c4*4, src + (size_t)r*32 + c4);
        }
    };

    int tile = blockIdx.x;
    const int stride = gridDim.x;
    if (tile < P1_NT) load_tile(tile, 0);
    cp_commit();
    int par = 0;
    for (; tile < P1_NT; tile += stride) {
        int nxt = tile + stride;
        if (nxt < P1_NT) load_tile(nxt, par ^ 1);
        cp_commit();
        cp_wait1();
        __syncthreads();

        float c[2][4] = {};
        const float* A = As + par*P1_TILE*P1_AS + warp*16*P1_AS;
        #pragma unroll
        for (int kk = 0; kk < 16; kk++) {
            float a0f = A[ g     *P1_AS + kk*8 + t    ];
            float a1f = A[(g + 8)*P1_AS + kk*8 + t    ];
            float a2f = A[ g     *P1_AS + kk*8 + t + 4];
            float a3f = A[(g + 8)*P1_AS + kk*8 + t + 4];
            unsigned ah[4] = {cvt_tf32(a0f), cvt_tf32(a1f), cvt_tf32(a2f), cvt_tf32(a3f)};
            unsigned al[4] = {
                cvt_tf32(a0f - __uint_as_float(ah[0])),
                cvt_tf32(a1f - __uint_as_float(ah[1])),
                cvt_tf32(a2f - __uint_as_float(ah[2])),
                cvt_tf32(a3f - __uint_as_float(ah[3]))};
            #pragma unroll
            for (int nt = 0; nt < 2; nt++) {
                unsigned bl0 = __float_as_uint(blo[((kk*2 + nt)*2 + 0)*32 + lane]);
                unsigned bl1 = __float_as_uint(blo[((kk*2 + nt)*2 + 1)*32 + lane]);
                mma_tf32(c[nt], ah, bhi[kk][nt][0], bhi[kk][nt][1]); // hi*hi
                mma_tf32(c[nt], al, bhi[kk][nt][0], bhi[kk][nt][1]); // lo*hi
                mma_tf32(c[nt], ah, bl0, bl1);                      // hi*lo
            }
        }
        float* out = e12 + ((size_t)tile*P1_TILE + warp*16)*16;
        #pragma unroll
        for (int nt = 0; nt < 2; nt++) {
            *(float2*)&out[ g     *16 + nt*8 + 2*t] = make_float2(c[nt][0], c[nt][1]);
            *(float2*)&out[(g + 8)*16 + nt*8 + 2*t] = make_float2(c[nt][2], c[nt][3]);
        }
        __syncthreads();
        par ^= 1;
    }
}

// ---------------- PASS 2: streaming attention (online softmax, no max) -----
// grid: 256 blocks (b, 8 i-rows). 256 threads: tid -> (i local, h, c-quad s).
__global__ void __launch_bounds__(256) attn2_k(
    const float* __restrict__ qkv, const float* __restrict__ e12,
    float* __restrict__ yout)
{
    const int tid = threadIdx.x;
    const int b  = blockIdx.x >> 6;
    const int i  = (blockIdx.x & 63)*8 + (tid >> 5);
    const int h  = (tid >> 2) & 7;
    const int s  = tid & 3;

    float4 q = *(const float4*)(qkv + ((size_t)(b*Nv + i)*384) + h*16 + s*4);
    q.x *= 0.25f; q.y *= 0.25f; q.z *= 0.25f; q.w *= 0.25f;

    const float* kbase = qkv + (size_t)b*Nv*384 + 128 + h*16 + s*4;
    const float* vbase = kbase + 128;
    const float* ebase = e12 + (size_t)(b*Nv + i)*Nv*16 + h*2;

    float4 acc = make_float4(0.f, 0.f, 0.f, 0.f);
    float sden = 0.f;
    #pragma unroll 4
    for (int j = 0; j < Nv; j++) {
        float4 kv = *(const float4*)(kbase + (size_t)j*384);
        float part = q.x*kv.x;
        part = fmaf(q.y, kv.y, part);
        part = fmaf(q.z, kv.z, part);
        part = fmaf(q.w, kv.w, part);
        part += __shfl_xor_sync(0xffffffffu, part, 1);
        part += __shfl_xor_sync(0xffffffffu, part, 2);
        float2 ee = *(const float2*)(ebase + (size_t)j*16);
        float p  = __expf(part + ee.x);
        float pe = p * ee.y;
        sden += p;
        float4 vv = *(const float4*)(vbase + (size_t)j*384);
        acc.x = fmaf(pe, vv.x, acc.x);
        acc.y = fmaf(pe, vv.y, acc.y);
        acc.z = fmaf(pe, vv.z, acc.z);
        acc.w = fmaf(pe, vv.w, acc.w);
    }
    float inv = 1.0f / sden;
    ((float4*)(yout + (size_t)(b*Nv + i)*Dv))[h*4 + s] =
        make_float4(acc.x*inv, acc.y*inv, acc.z*inv, acc.w*inv);
}

// ---------------- host launch ----------------------------------------------
extern "C" void kernel_launch(void* const* d_in, const int* in_sizes, int n_in,
                              void* d_out, int out_size) {
    const float* h    = (const float*)d_in[0];
    const float* e    = (const float*)d_in[1];
    const float* W_h  = (const float*)d_in[2];
    const float* W_e  = (const float*)d_in[3];
    const float* n1   = (const float*)d_in[4];
    const float* n2   = (const float*)d_in[5];
    const float* W_fc = (const float*)d_in[6];
    const float* W_pr = (const float*)d_in[7];
    float* out = (float*)d_out;

    float *p_hn, *p_qkv, *p_y, *p_z, *p_hid, *p_e12;
    cudaGetSymbolAddress((void**)&p_hn,  g_hn);
    cudaGetSymbolAddress((void**)&p_qkv, g_qkv);
    cudaGetSymbolAddress((void**)&p_y,   g_y);
    cudaGetSymbolAddress((void**)&p_z,   g_z);
    cudaGetSymbolAddress((void**)&p_hid, g_hid);
    cudaGetSymbolAddress((void**)&p_e12, g_e12);

    cudaFuncSetAttribute(eproj_k, cudaFuncAttributeMaxDynamicSharedMemorySize, P1_SMEM);

    // 1) hn = rmsnorm(h)
    rmsnorm_k<<<ROWS/8, 256>>>(h, nullptr, n1, p_hn);
    // 2) qkv = hn @ W_h
    gemm64<false,false><<<dim3(384/64, ROWS/64), 256>>>(p_hn, W_h, nullptr, p_qkv,
                                                        ROWS, 3*Dv, Dv);
    // 3a) e12 = e @ W_e (tf32 mma, streaming)
    eproj_k<<<148, 256, P1_SMEM>>>(e, W_e, p_e12);
    // 3b) attention with precomputed e1/e2 -> y
    attn2_k<<<Bv*(Nv/8), 256>>>(p_qkv, p_e12, p_y);
    // 4) z = rmsnorm(y + h)
    rmsnorm_k<<<ROWS/8, 256>>>(p_y, h, n2, p_z);
    // 5) hid = gelu(z @ W_fc)
    gemm64<true,false><<<dim3(FFv/64, ROWS/64), 256>>>(p_z, W_fc, nullptr, p_hid,
                                                       ROWS, FFv, Dv);
    // 6) out = hid @ W_proj + y
    gemm64<false,true><<<dim3(Dv/64, ROWS/64), 256>>>(p_hid, W_pr, p_y, out,
                                                      ROWS, Dv, FFv);
}